// round 1
// baseline (speedup 1.0000x reference)
#include <cuda_runtime.h>

// Blocks_86096914416144 — SNN block scan.
// Shapes: x [T=1024, B=32, N=1024] f32; beta_raw/p_raw/b_raw [N] f32.
// Out: spikes [T, B, N] f32.
//
// Key insight: the scan is independent per (b, n) lane. Carry per lane:
//   z[8] (integer-valued floats), scalar a (a_kernel[t] == p^(t+1) * a),
//   scalar int_mem. One thread per lane, 128 sequential block iterations,
//   pure HBM streaming (268 MB total traffic).

#define T_LEN   1024
#define TB      8
#define NBLK    (T_LEN / TB)      // 128
#define BATCH   32
#define NOUT    1024
#define BN      (BATCH * NOUT)    // 32768

__global__ __launch_bounds__(64)
void blocks_snn_kernel(const float* __restrict__ x,
                       const float* __restrict__ beta_raw,
                       const float* __restrict__ p_raw,
                       const float* __restrict__ b_raw,
                       float* __restrict__ out)
{
    const int tid = blockIdx.x * blockDim.x + threadIdx.x;   // 0..32767
    const int n   = tid & (NOUT - 1);

    // clamped per-neuron properties (match jnp.clip / abs ordering)
    const float beta  = fminf(fmaxf(beta_raw[n], 0.001f), 0.999f);
    const float p     = fminf(fmaxf(fabsf(p_raw[n]), 0.0f), 0.999f);
    const float bb    = fminf(fmaxf(fabsf(b_raw[n]), 0.001f), 1.0f);
    const float inv_p = 1.0f / p;

    // beta^k, k = 0..7  (reference: beta ** (t-s) via pow)
    float bpow[TB];
    bpow[0] = 1.0f;
    #pragma unroll
    for (int k = 1; k < TB; k++) bpow[k] = powf(beta, (float)k);

    // p^k, k = 0..8  (p_pow = p ** [1..8]; also p^decay_steps lookup)
    float ppow[TB + 1];
    ppow[0] = 1.0f;
    #pragma unroll
    for (int k = 1; k <= TB; k++) ppow[k] = powf(p, (float)k);

    // carry state
    float z[TB];
    #pragma unroll
    for (int t = 0; t < TB; t++) z[t] = 0.0f;
    float a    = 0.0f;   // scalar form of a_kernel
    float vmem = 0.0f;   // int_mem

    const float* xp = x + tid;
    float*       op = out + tid;

    // register double-buffer for x (prefetch one block ahead)
    float xc[TB], xn[TB];
    #pragma unroll
    for (int t = 0; t < TB; t++) xc[t] = xp[t * BN];

    for (int blk = 0; blk < NBLK; blk++) {
        // ---- prefetch next block's inputs (independent of compute) ----
        if (blk + 1 < NBLK) {
            const float* xnx = xp + (size_t)(blk + 1) * TB * BN;
            #pragma unroll
            for (int t = 0; t < TB; t++) xn[t] = xnx[t * BN];
        }

        // ---- sg (prev spikes) and maskf ----
        float sg[TB];
        float maskf = 0.0f;
        #pragma unroll
        for (int t = 0; t < TB; t++) {
            sg[t] = (z[t] == 1.0f) ? 1.0f : 0.0f;
            if (sg[t] != 0.0f) maskf = 1.0f;
        }

        // ---- adaptation update ----
        // a_at_spike = sum_t a_kernel[t]*sg[t] + inv_p, a_kernel[t] = p^(t+1)*a
        float a_at = 0.0f;
        #pragma unroll
        for (int t = 0; t < TB; t++)
            if (sg[t] != 0.0f) a_at += ppow[t + 1] * a;
        a_at += inv_p;

        int ds = 0;                         // decay_steps = count(z > 1)
        #pragma unroll
        for (int t = 0; t < TB; t++)
            if (z[t] > 1.0f) ds++;

        float pds = ppow[0];                // p^decay_steps (select, stays in regs)
        #pragma unroll
        for (int k = 1; k <= TB; k++)
            if (ds == k) pds = ppow[k];

        const float new_a = a_at * pds;
        // a = a_kernel_prev[-1]*(1-maskf) + new_a*maskf, exact select (maskf in {0,1})
        a = (maskf != 0.0f) ? new_a : (ppow[TB] * a);

        // ---- refractory input masking + initial membrane carry-in ----
        const float v_init = vmem * (1.0f - maskf);
        float cur[TB];
        #pragma unroll
        for (int t = 0; t < TB; t++)
            cur[t] = (z[t] < maskf) ? 0.0f : xc[t];
        cur[0] = cur[0] + beta * v_init;

        // ---- causal decayed sum (einsum 'tsn,sbn->tbn'), threshold ----
        float f[TB];
        float mlast = 0.0f;
        #pragma unroll
        for (int t = 0; t < TB; t++) {
            float m = 0.0f;
            #pragma unroll
            for (int s = 0; s <= t; s++)
                m += bpow[t - s] * cur[s];     // ascending-s, matches reference
            const float vth = 1.0f + bb * (ppow[t + 1] * a);
            f[t] = ((m - vth) > 0.0f) ? 1.0f : 0.0f;
            if (t == TB - 1) mlast = m;
        }

        // ---- z_new = phi-cumsum (exact small integers), output spikes ----
        float c = 0.0f, zr = 0.0f;
        #pragma unroll
        for (int t = 0; t < TB; t++) {
            c  += f[t];
            zr += c;
            z[t] = zr;
        }

        float* ob = op + (size_t)blk * TB * BN;
        #pragma unroll
        for (int t = 0; t < TB; t++)
            ob[t * BN] = (z[t] == 1.0f) ? 1.0f : 0.0f;

        vmem = mlast;

        #pragma unroll
        for (int t = 0; t < TB; t++) xc[t] = xn[t];
    }
}

extern "C" void kernel_launch(void* const* d_in, const int* in_sizes, int n_in,
                              void* d_out, int out_size)
{
    const float* x        = (const float*)d_in[0];
    const float* beta_raw = (const float*)d_in[1];
    const float* p_raw    = (const float*)d_in[2];
    const float* b_raw    = (const float*)d_in[3];
    float* out = (float*)d_out;

    // 32768 lanes, 64 threads/CTA -> 512 CTAs (~3.5/SM, ~7 warps/SM)
    blocks_snn_kernel<<<BN / 64, 64>>>(x, beta_raw, p_raw, b_raw, out);
}

// round 2
// speedup vs baseline: 1.8958x; 1.8958x over previous
#include <cuda_runtime.h>

// Blocks_86096914416144 — SNN block scan, R2: deep (3-block-ahead) register
// prefetch to cover DRAM latency. Scan is independent per (b,n) lane; carry is
// z[8] + scalar a + scalar vmem. Numerics identical to R1 (rel_err 0.0).

#define T_LEN   1024
#define TB      8
#define NBLK    (T_LEN / TB)      // 128
#define BATCH   32
#define NOUT    1024
#define BN      (BATCH * NOUT)    // 32768

struct LaneState {
    float z[TB];
    float a;
    float vmem;
};

// One block-iteration of the scan. All numerics ordered exactly as R1.
__device__ __forceinline__
void step_block(LaneState& st,
                const float* __restrict__ xc,   // this block's 8 inputs (regs)
                float* __restrict__ ob,          // output ptr for this block
                float beta, float bb, float inv_p,
                const float* __restrict__ bpow,  // beta^0..7
                const float* __restrict__ ppow)  // p^0..8
{
    // sg (prev spikes) and maskf
    float sg[TB];
    float maskf = 0.0f;
    #pragma unroll
    for (int t = 0; t < TB; t++) {
        sg[t] = (st.z[t] == 1.0f) ? 1.0f : 0.0f;
        if (sg[t] != 0.0f) maskf = 1.0f;
    }

    // adaptation: a_at_spike = sum_t p^(t+1)*a*sg[t] + 1/p
    float a_at = 0.0f;
    #pragma unroll
    for (int t = 0; t < TB; t++)
        if (sg[t] != 0.0f) a_at += ppow[t + 1] * st.a;
    a_at += inv_p;

    int ds = 0;                         // decay_steps = count(z > 1)
    #pragma unroll
    for (int t = 0; t < TB; t++)
        if (st.z[t] > 1.0f) ds++;

    float pds = ppow[0];
    #pragma unroll
    for (int k = 1; k <= TB; k++)
        if (ds == k) pds = ppow[k];

    const float new_a = a_at * pds;
    st.a = (maskf != 0.0f) ? new_a : (ppow[TB] * st.a);

    // refractory masking + membrane carry-in
    const float v_init = st.vmem * (1.0f - maskf);
    float cur[TB];
    #pragma unroll
    for (int t = 0; t < TB; t++)
        cur[t] = (st.z[t] < maskf) ? 0.0f : xc[t];
    cur[0] = cur[0] + beta * v_init;

    // causal decayed sum + threshold
    float f[TB];
    float mlast = 0.0f;
    #pragma unroll
    for (int t = 0; t < TB; t++) {
        float m = 0.0f;
        #pragma unroll
        for (int s = 0; s <= t; s++)
            m += bpow[t - s] * cur[s];
        const float vth = 1.0f + bb * (ppow[t + 1] * st.a);
        f[t] = ((m - vth) > 0.0f) ? 1.0f : 0.0f;
        if (t == TB - 1) mlast = m;
    }

    // z = double cumsum of f (exact small integers); emit spikes (z == 1)
    float c = 0.0f, zr = 0.0f;
    #pragma unroll
    for (int t = 0; t < TB; t++) {
        c  += f[t];
        zr += c;
        st.z[t] = zr;
        ob[t * BN] = (zr == 1.0f) ? 1.0f : 0.0f;
    }

    st.vmem = mlast;
}

__global__ __launch_bounds__(64)
void blocks_snn_kernel(const float* __restrict__ x,
                       const float* __restrict__ beta_raw,
                       const float* __restrict__ p_raw,
                       const float* __restrict__ b_raw,
                       float* __restrict__ out)
{
    const int tid = blockIdx.x * blockDim.x + threadIdx.x;   // 0..32767
    const int n   = tid & (NOUT - 1);

    const float beta  = fminf(fmaxf(beta_raw[n], 0.001f), 0.999f);
    const float p     = fminf(fmaxf(fabsf(p_raw[n]), 0.0f), 0.999f);
    const float bb    = fminf(fmaxf(fabsf(b_raw[n]), 0.001f), 1.0f);
    const float inv_p = 1.0f / p;

    float bpow[TB];
    bpow[0] = 1.0f;
    #pragma unroll
    for (int k = 1; k < TB; k++) bpow[k] = powf(beta, (float)k);

    float ppow[TB + 1];
    ppow[0] = 1.0f;
    #pragma unroll
    for (int k = 1; k <= TB; k++) ppow[k] = powf(p, (float)k);

    LaneState st;
    #pragma unroll
    for (int t = 0; t < TB; t++) st.z[t] = 0.0f;
    st.a = 0.0f;
    st.vmem = 0.0f;

    const float* xp = x + tid;
    float*       op = out + tid;

    // 4-slot register ring, prefetch 3 blocks ahead
    float buf[4][TB];
    #pragma unroll
    for (int pb = 0; pb < 3; pb++) {
        const float* xb = xp + (size_t)pb * TB * BN;
        #pragma unroll
        for (int t = 0; t < TB; t++) buf[pb][t] = xb[t * BN];
    }

    #pragma unroll 1
    for (int g = 0; g < NBLK / 4; g++) {
        #pragma unroll
        for (int u = 0; u < 4; u++) {
            const int blk = 4 * g + u;
            // prefetch blk+3 into the slot freed last iteration
            if (blk + 3 < NBLK) {
                const float* xb = xp + (size_t)(blk + 3) * TB * BN;
                #pragma unroll
                for (int t = 0; t < TB; t++)
                    buf[(u + 3) & 3][t] = xb[t * BN];
            }
            step_block(st, buf[u & 3], op + (size_t)blk * TB * BN,
                       beta, bb, inv_p, bpow, ppow);
        }
    }
}

extern "C" void kernel_launch(void* const* d_in, const int* in_sizes, int n_in,
                              void* d_out, int out_size)
{
    const float* x        = (const float*)d_in[0];
    const float* beta_raw = (const float*)d_in[1];
    const float* p_raw    = (const float*)d_in[2];
    const float* b_raw    = (const float*)d_in[3];
    float* out = (float*)d_out;

    blocks_snn_kernel<<<BN / 64, 64>>>(x, beta_raw, p_raw, b_raw, out);
}